// round 7
// baseline (speedup 1.0000x reference)
#include <cuda_runtime.h>
#include <cuda_bf16.h>
#include <cstdint>

#define N_NODES 50000
#define E_EDGES 500000
#define H_DIM   128
#define ROW_F   512          // 4 channels * 128 floats per node

// ---------------------------------------------------------------------------
// Global scratch
// ---------------------------------------------------------------------------
__device__ float         g_agg[(size_t)N_NODES * ROW_F];
__device__ __nv_bfloat16 g_Whi[4 * 128 * 256];   // [c][n][k] hi halves
__device__ __nv_bfloat16 g_Wlo[4 * 128 * 256];   // [c][n][k] lo residuals
__device__ int g_is64;
__device__ int g_cnt[N_NODES];
__device__ int g_off[N_NODES + 1];
__device__ int g_cur[N_NODES];
__device__ int g_cols[E_EDGES];

// ---------------------------------------------------------------------------
// helpers
// ---------------------------------------------------------------------------
__device__ __forceinline__ uint32_t smem_u32(const void* p) {
    uint32_t a;
    asm("{ .reg .u64 t; cvta.to.shared.u64 t, %1; cvt.u32.u64 %0, t; }"
        : "=r"(a) : "l"(p));
    return a;
}

// pack two f32 into bf16x2 (lo arg -> low half, hi arg -> high half)
__device__ __forceinline__ uint32_t cvt_bf16x2(float lo, float hi) {
    uint32_t r;
    asm("cvt.rn.bf16x2.f32 %0, %1, %2;" : "=r"(r) : "f"(hi), "f"(lo));
    return r;
}

#define SW128(o) ((o) ^ (((o) >> 3) & 0x70))

__device__ __forceinline__ void ldsm_x4(uint32_t addr, uint32_t& r0, uint32_t& r1,
                                        uint32_t& r2, uint32_t& r3) {
    asm volatile("ldmatrix.sync.aligned.m8n8.x4.shared.b16 {%0,%1,%2,%3}, [%4];"
                 : "=r"(r0), "=r"(r1), "=r"(r2), "=r"(r3) : "r"(addr));
}

__device__ __forceinline__ void mma16816(float* c, const uint32_t* a,
                                         uint32_t b0, uint32_t b1) {
    asm volatile(
        "mma.sync.aligned.m16n8k16.row.col.f32.bf16.bf16.f32 "
        "{%0,%1,%2,%3}, {%4,%5,%6,%7}, {%8,%9}, {%0,%1,%2,%3};"
        : "+f"(c[0]), "+f"(c[1]), "+f"(c[2]), "+f"(c[3])
        : "r"(a[0]), "r"(a[1]), "r"(a[2]), "r"(a[3]), "r"(b0), "r"(b1));
}

__device__ __forceinline__ void cp_async16(uint32_t smem_addr, const void* gptr) {
    asm volatile("cp.async.cg.shared.global [%0], [%1], 16;"
                 :: "r"(smem_addr), "l"(gptr) : "memory");
}
__device__ __forceinline__ void cp_commit() {
    asm volatile("cp.async.commit_group;" ::: "memory");
}
__device__ __forceinline__ void cp_wait0() {
    asm volatile("cp.async.wait_group 0;" ::: "memory");
}

// ---------------------------------------------------------------------------
// edge index fetch with dtype branch
// ---------------------------------------------------------------------------
__device__ __forceinline__ int edge_idx(const void* ei_raw, size_t i) {
    if (g_is64) return (int)((const long long*)ei_raw)[i];
    return ((const int*)ei_raw)[i];
}

__global__ void detect_dtype_kernel(const int* __restrict__ ei32) {
    int all_zero = 1;
    for (int i = 0; i < 128; i++) {
        if (ei32[2 * i + 1] != 0) { all_zero = 0; break; }
    }
    g_is64 = all_zero;
}

// ---------------------------------------------------------------------------
// Weight prep: split stacked weights into bf16 hi + lo residual, [c][n][k]
// ---------------------------------------------------------------------------
__global__ void prep_weights_kernel(const float* __restrict__ Wsrel,
                                    const float* __restrict__ Wsroot,
                                    const float* __restrict__ Wvrel,
                                    const float* __restrict__ Wvroot) {
    int n = blockIdx.x;
    int c = blockIdx.y;
    int k = threadIdx.x;
    const float* root = (c == 0) ? Wsroot : Wvroot;
    const float* rel  = (c == 0) ? Wsrel  : Wvrel;
    float w = (k < 128) ? __ldg(root + n * 128 + k)
                        : __ldg(rel  + n * 128 + (k - 128));
    __nv_bfloat16 h = __float2bfloat16(w);
    float hf = __bfloat162float(h);
    __nv_bfloat16 l = __float2bfloat16(w - hf);
    size_t o = ((size_t)(c * 128 + n)) * 256 + k;
    g_Whi[o] = h;
    g_Wlo[o] = l;
}

// ---------------------------------------------------------------------------
// CSR build
// ---------------------------------------------------------------------------
__global__ void zero_cnt_kernel() {
    int i = blockIdx.x * blockDim.x + threadIdx.x;
    if (i < N_NODES) g_cnt[i] = 0;
}

__global__ __launch_bounds__(256)
void hist_kernel(const void* __restrict__ ei_raw) {
    int e = blockIdx.x * blockDim.x + threadIdx.x;
    if (e < E_EDGES) atomicAdd(&g_cnt[edge_idx(ei_raw, e)], 1);
}

// Warp-shuffle based single-block scan (3 syncs per 1024-chunk).
__global__ __launch_bounds__(1024)
void scan_kernel() {
    __shared__ int wsum[32];
    __shared__ int carry_s;
    const int tid  = threadIdx.x;
    const int lane = tid & 31;
    const int w    = tid >> 5;
    if (tid == 0) carry_s = 0;
    __syncthreads();

    for (int base = 0; base < N_NODES; base += 1024) {
        int i = base + tid;
        int v = (i < N_NODES) ? g_cnt[i] : 0;
        int incl = v;
        #pragma unroll
        for (int d = 1; d < 32; d <<= 1) {
            int t = __shfl_up_sync(0xFFFFFFFFu, incl, d);
            if (lane >= d) incl += t;
        }
        if (lane == 31) wsum[w] = incl;
        __syncthreads();
        if (w == 0) {
            int s = wsum[lane];
            #pragma unroll
            for (int d = 1; d < 32; d <<= 1) {
                int t = __shfl_up_sync(0xFFFFFFFFu, s, d);
                if (lane >= d) s += t;
            }
            wsum[lane] = s;
        }
        __syncthreads();
        int wbase = (w > 0) ? wsum[w - 1] : 0;
        int excl = carry_s + wbase + incl - v;
        if (i < N_NODES) {
            g_off[i] = excl;
            g_cur[i] = excl;
        }
        int total = wsum[31];
        __syncthreads();
        if (tid == 0) carry_s += total;
        __syncthreads();
    }
    if (tid == 0) g_off[N_NODES] = carry_s;
}

__global__ __launch_bounds__(256)
void scatter_kernel(const void* __restrict__ ei_raw) {
    int e = blockIdx.x * blockDim.x + threadIdx.x;
    if (e < E_EDGES) {
        int row = edge_idx(ei_raw, e);
        int col = edge_idx(ei_raw, (size_t)E_EDGES + e);
        int pos = atomicAdd(&g_cur[row], 1);
        g_cols[pos] = col;
    }
}

// ---------------------------------------------------------------------------
// CSR aggregation, unrolled x4 for gather MLP
// ---------------------------------------------------------------------------
__global__ __launch_bounds__(256)
void csr_agg_kernel(const float* __restrict__ x) {
    int node = blockIdx.x * 2 + (threadIdx.x >> 7);
    int lane = threadIdx.x & 127;
    if (node >= N_NODES) return;

    int beg = __ldg(&g_off[node]);
    int end = __ldg(&g_off[node + 1]);

    float4 a0 = make_float4(0.f, 0.f, 0.f, 0.f);
    float4 a1 = make_float4(0.f, 0.f, 0.f, 0.f);
    float4 a2 = make_float4(0.f, 0.f, 0.f, 0.f);
    float4 a3 = make_float4(0.f, 0.f, 0.f, 0.f);
    int j = beg;
    for (; j + 3 < end; j += 4) {
        int c0 = __ldg(&g_cols[j]);
        int c1 = __ldg(&g_cols[j + 1]);
        int c2 = __ldg(&g_cols[j + 2]);
        int c3 = __ldg(&g_cols[j + 3]);
        float4 v0 = __ldg((const float4*)(x + (size_t)c0 * ROW_F) + lane);
        float4 v1 = __ldg((const float4*)(x + (size_t)c1 * ROW_F) + lane);
        float4 v2 = __ldg((const float4*)(x + (size_t)c2 * ROW_F) + lane);
        float4 v3 = __ldg((const float4*)(x + (size_t)c3 * ROW_F) + lane);
        a0.x += v0.x; a0.y += v0.y; a0.z += v0.z; a0.w += v0.w;
        a1.x += v1.x; a1.y += v1.y; a1.z += v1.z; a1.w += v1.w;
        a2.x += v2.x; a2.y += v2.y; a2.z += v2.z; a2.w += v2.w;
        a3.x += v3.x; a3.y += v3.y; a3.z += v3.z; a3.w += v3.w;
    }
    for (; j < end; j++) {
        int c0 = __ldg(&g_cols[j]);
        float4 v0 = __ldg((const float4*)(x + (size_t)c0 * ROW_F) + lane);
        a0.x += v0.x; a0.y += v0.y; a0.z += v0.z; a0.w += v0.w;
    }
    a0.x += a1.x + a2.x + a3.x;
    a0.y += a1.y + a2.y + a3.y;
    a0.z += a1.z + a2.z + a3.z;
    a0.w += a1.w + a2.w + a3.w;
    ((float4*)(g_agg + (size_t)node * ROW_F))[lane] = a0;
}

// ---------------------------------------------------------------------------
// Transform: split-bf16 HMMA GEMM.
//   W tiles via cp.async (bf16, no conversion), A fp32 register-prefetched
//   one chunk ahead so LDGs overlap the MMA phase.
// ---------------------------------------------------------------------------
#define SM_AHI 0
#define SM_ALO 16384
#define SM_WHI 32768
#define SM_WLO 49152
#define SM_TOTAL 65536

__global__ __launch_bounds__(256, 2)
void transform_mma_kernel(const float* __restrict__ x,
                          const float* __restrict__ bsr,
                          float* __restrict__ out) {
    extern __shared__ char smem[];
    const uint32_t sb = smem_u32(smem);
    const int tid  = threadIdx.x;
    const int wid  = tid >> 5;
    const int lane = tid & 31;
    const int c      = blockIdx.y;
    const int node0  = blockIdx.x * 128;
    const int warp_m = (wid & 3) * 32;   // 4 warps along m
    const int warp_n = (wid >> 2) * 64;  // 2 warps along n

    float acc[2][8][4];
    #pragma unroll
    for (int mt = 0; mt < 2; mt++)
        #pragma unroll
        for (int j = 0; j < 8; j++)
            #pragma unroll
            for (int q = 0; q < 4; q++) acc[mt][j][q] = 0.f;

    const float* agg = g_agg;

    // ldmatrix lane-address components
    const int a_row_l = lane & 15;
    const int a_koff  = (lane >> 4) << 4;
    const int b_row_l = ((lane >> 4) << 3) + (lane & 7);
    const int b_koff  = ((lane >> 3) & 1) << 4;

    // per-thread A tile coords (reused every chunk)
    const int aq = tid & 15;               // float4 within 64-float row
    const int am = tid >> 4;               // base node row (+16 per it)
    const uint32_t a_sw[8] = {
        SW128((uint32_t)((am +   0) * 128 + aq * 8)),
        SW128((uint32_t)((am +  16) * 128 + aq * 8)),
        SW128((uint32_t)((am +  32) * 128 + aq * 8)),
        SW128((uint32_t)((am +  48) * 128 + aq * 8)),
        SW128((uint32_t)((am +  64) * 128 + aq * 8)),
        SW128((uint32_t)((am +  80) * 128 + aq * 8)),
        SW128((uint32_t)((am +  96) * 128 + aq * 8)),
        SW128((uint32_t)((am + 112) * 128 + aq * 8)),
    };

    // A register staging
    float4 areg[8];
    {
        const float* src = x;                       // chunk 0
        const int koff = c * H_DIM;
        #pragma unroll
        for (int it = 0; it < 8; it++) {
            int node = node0 + am + it * 16;
            areg[it] = (node < N_NODES)
                ? __ldg((const float4*)(src + (size_t)node * ROW_F + koff) + aq)
                : make_float4(0.f, 0.f, 0.f, 0.f);
        }
    }

    for (int kc = 0; kc < 4; kc++) {
        // ---- issue W cp.async (bf16 hi/lo, SW128 dst) ----
        {
            const size_t kbase = (size_t)(c * 128) * 256 + kc * 64;
            #pragma unroll
            for (int it = 0; it < 4; it++) {
                int idx = tid + it * 256;        // 0..1023
                int u = idx & 7;                 // 16B unit within 128B row
                int n = idx >> 3;                // output row
                uint32_t sw = SW128((uint32_t)(n * 128 + u * 16));
                const __nv_bfloat16* gh = g_Whi + kbase + (size_t)n * 256 + u * 8;
                const __nv_bfloat16* gl = g_Wlo + kbase + (size_t)n * 256 + u * 8;
                cp_async16(sb + SM_WHI + sw, gh);
                cp_async16(sb + SM_WLO + sw, gl);
            }
            cp_commit();
        }

        // ---- convert + store A regs (current chunk) ----
        #pragma unroll
        for (int it = 0; it < 8; it++) {
            float4 v = areg[it];
            float hx = __bfloat162float(__float2bfloat16(v.x));
            float hy = __bfloat162float(__float2bfloat16(v.y));
            float hz = __bfloat162float(__float2bfloat16(v.z));
            float hw = __bfloat162float(__float2bfloat16(v.w));
            uint2 hi = make_uint2(cvt_bf16x2(v.x, v.y), cvt_bf16x2(v.z, v.w));
            uint2 lo = make_uint2(cvt_bf16x2(v.x - hx, v.y - hy),
                                  cvt_bf16x2(v.z - hz, v.w - hw));
            *(uint2*)(smem + SM_AHI + a_sw[it]) = hi;
            *(uint2*)(smem + SM_ALO + a_sw[it]) = lo;
        }

        // ---- prefetch next chunk's A into regs (flies during MMA) ----
        if (kc < 3) {
            const int kn = kc + 1;
            const float* src = (kn < 2) ? x : agg;
            const int koff = (kn & 1) * 64 + c * H_DIM;
            #pragma unroll
            for (int it = 0; it < 8; it++) {
                int node = node0 + am + it * 16;
                areg[it] = (node < N_NODES)
                    ? __ldg((const float4*)(src + (size_t)node * ROW_F + koff) + aq)
                    : make_float4(0.f, 0.f, 0.f, 0.f);
            }
        }

        cp_wait0();
        __syncthreads();

        // ---- compute: 4 k16-steps ----
        #pragma unroll
        for (int ks = 0; ks < 4; ks++) {
            uint32_t ah[2][4], al[2][4];
            #pragma unroll
            for (int mt = 0; mt < 2; mt++) {
                uint32_t boff = (uint32_t)((warp_m + mt * 16 + a_row_l) * 128
                                           + ks * 32 + a_koff);
                uint32_t sw = SW128(boff);
                ldsm_x4(sb + SM_AHI + sw, ah[mt][0], ah[mt][1], ah[mt][2], ah[mt][3]);
                ldsm_x4(sb + SM_ALO + sw, al[mt][0], al[mt][1], al[mt][2], al[mt][3]);
            }
            #pragma unroll
            for (int np = 0; np < 4; np++) {
                uint32_t boff = (uint32_t)((warp_n + np * 16 + b_row_l) * 128
                                           + ks * 32 + b_koff);
                uint32_t sw = SW128(boff);
                uint32_t bh0, bh1, bh2, bh3, bl0, bl1, bl2, bl3;
                ldsm_x4(sb + SM_WHI + sw, bh0, bh1, bh2, bh3);
                ldsm_x4(sb + SM_WLO + sw, bl0, bl1, bl2, bl3);
                #pragma unroll
                for (int mt = 0; mt < 2; mt++) {
                    mma16816(acc[mt][np * 2 + 0], ah[mt], bh0, bh1);
                    mma16816(acc[mt][np * 2 + 0], al[mt], bh0, bh1);
                    mma16816(acc[mt][np * 2 + 0], ah[mt], bl0, bl1);
                    mma16816(acc[mt][np * 2 + 1], ah[mt], bh2, bh3);
                    mma16816(acc[mt][np * 2 + 1], al[mt], bh2, bh3);
                    mma16816(acc[mt][np * 2 + 1], ah[mt], bl2, bl3);
                }
            }
        }
        __syncthreads();
    }

    // ---- epilogue ----
    const int erow = lane >> 2;
    const int ecol = (lane & 3) * 2;
    #pragma unroll
    for (int mt = 0; mt < 2; mt++) {
        #pragma unroll
        for (int j = 0; j < 8; j++) {
            int col = warp_n + j * 8 + ecol;
            float b0 = 0.f, b1 = 0.f;
            if (c == 0) { b0 = __ldg(bsr + col); b1 = __ldg(bsr + col + 1); }
            int r0 = node0 + warp_m + mt * 16 + erow;
            int r1 = r0 + 8;
            if (r0 < N_NODES) {
                float2 v = make_float2(acc[mt][j][0] + b0, acc[mt][j][1] + b1);
                *(float2*)(out + (size_t)r0 * ROW_F + (size_t)c * H_DIM + col) = v;
            }
            if (r1 < N_NODES) {
                float2 v = make_float2(acc[mt][j][2] + b0, acc[mt][j][3] + b1);
                *(float2*)(out + (size_t)r1 * ROW_F + (size_t)c * H_DIM + col) = v;
            }
        }
    }
}

// ---------------------------------------------------------------------------
// Launch
// ---------------------------------------------------------------------------
extern "C" void kernel_launch(void* const* d_in, const int* in_sizes, int n_in,
                              void* d_out, int out_size) {
    const float* x      = (const float*)d_in[0];
    const void*  ei     = d_in[1];
    const float* Wsrel  = (const float*)d_in[2];
    const float* Wsroot = (const float*)d_in[3];
    const float* bsr    = (const float*)d_in[4];
    const float* Wvrel  = (const float*)d_in[5];
    const float* Wvroot = (const float*)d_in[6];
    float*       out    = (float*)d_out;

    cudaFuncSetAttribute(transform_mma_kernel,
                         cudaFuncAttributeMaxDynamicSharedMemorySize, SM_TOTAL);

    // Phase 0: dtype detect + weight split
    detect_dtype_kernel<<<1, 1>>>((const int*)ei);
    {
        dim3 grid(128, 4);
        prep_weights_kernel<<<grid, 256>>>(Wsrel, Wsroot, Wvrel, Wvroot);
    }

    // Phase 1: CSR build
    zero_cnt_kernel<<<(N_NODES + 255) / 256, 256>>>();
    hist_kernel<<<(E_EDGES + 255) / 256, 256>>>(ei);
    scan_kernel<<<1, 1024>>>();
    scatter_kernel<<<(E_EDGES + 255) / 256, 256>>>(ei);

    // Phase 2: CSR aggregation
    csr_agg_kernel<<<(N_NODES + 1) / 2, 256>>>(x);

    // Phase 3: transform (split-bf16 HMMA, cp.async W + reg-prefetch A)
    {
        dim3 grid((N_NODES + 127) / 128, 4);
        transform_mma_kernel<<<grid, 256, SM_TOTAL>>>(x, bsr, out);
    }
}

// round 8
// speedup vs baseline: 1.0524x; 1.0524x over previous
#include <cuda_runtime.h>
#include <cuda_bf16.h>
#include <cstdint>

#define N_NODES 50000
#define E_EDGES 500000
#define H_DIM   128
#define ROW_F   512          // 4 channels * 128 floats per node

// ---------------------------------------------------------------------------
// Global scratch
// ---------------------------------------------------------------------------
__device__ __nv_bfloat16 g_xhi[(size_t)N_NODES * ROW_F];
__device__ __nv_bfloat16 g_xlo[(size_t)N_NODES * ROW_F];
__device__ __nv_bfloat16 g_ahi[(size_t)N_NODES * ROW_F];
__device__ __nv_bfloat16 g_alo[(size_t)N_NODES * ROW_F];
__device__ __nv_bfloat16 g_Whi[4 * 128 * 256];   // [c][n][k] hi halves
__device__ __nv_bfloat16 g_Wlo[4 * 128 * 256];   // [c][n][k] lo residuals
__device__ int g_is64;
__device__ int g_cnt[N_NODES];
__device__ int g_off[N_NODES + 1];
__device__ int g_cur[N_NODES];
__device__ int g_cols[E_EDGES];

// ---------------------------------------------------------------------------
// helpers
// ---------------------------------------------------------------------------
__device__ __forceinline__ uint32_t smem_u32(const void* p) {
    uint32_t a;
    asm("{ .reg .u64 t; cvta.to.shared.u64 t, %1; cvt.u32.u64 %0, t; }"
        : "=r"(a) : "l"(p));
    return a;
}

// pack two f32 into bf16x2 (lo arg -> low half, hi arg -> high half)
__device__ __forceinline__ uint32_t cvt_bf16x2(float lo, float hi) {
    uint32_t r;
    asm("cvt.rn.bf16x2.f32 %0, %1, %2;" : "=r"(r) : "f"(hi), "f"(lo));
    return r;
}

#define SW128(o) ((o) ^ (((o) >> 3) & 0x70))

__device__ __forceinline__ void ldsm_x4(uint32_t addr, uint32_t& r0, uint32_t& r1,
                                        uint32_t& r2, uint32_t& r3) {
    asm volatile("ldmatrix.sync.aligned.m8n8.x4.shared.b16 {%0,%1,%2,%3}, [%4];"
                 : "=r"(r0), "=r"(r1), "=r"(r2), "=r"(r3) : "r"(addr));
}

__device__ __forceinline__ void mma16816(float* c, const uint32_t* a,
                                         uint32_t b0, uint32_t b1) {
    asm volatile(
        "mma.sync.aligned.m16n8k16.row.col.f32.bf16.bf16.f32 "
        "{%0,%1,%2,%3}, {%4,%5,%6,%7}, {%8,%9}, {%0,%1,%2,%3};"
        : "+f"(c[0]), "+f"(c[1]), "+f"(c[2]), "+f"(c[3])
        : "r"(a[0]), "r"(a[1]), "r"(a[2]), "r"(a[3]), "r"(b0), "r"(b1));
}

__device__ __forceinline__ void cp_async16(uint32_t smem_addr, const void* gptr) {
    asm volatile("cp.async.cg.shared.global [%0], [%1], 16;"
                 :: "r"(smem_addr), "l"(gptr) : "memory");
}
__device__ __forceinline__ void cp_commit() {
    asm volatile("cp.async.commit_group;" ::: "memory");
}
template <int N>
__device__ __forceinline__ void cp_wait() {
    asm volatile("cp.async.wait_group %0;" :: "n"(N) : "memory");
}

// split a float4 into hi/lo bf16x2 pairs
__device__ __forceinline__ void split4(float4 v, uint2& hi, uint2& lo) {
    float hx = __bfloat162float(__float2bfloat16(v.x));
    float hy = __bfloat162float(__float2bfloat16(v.y));
    float hz = __bfloat162float(__float2bfloat16(v.z));
    float hw = __bfloat162float(__float2bfloat16(v.w));
    hi = make_uint2(cvt_bf16x2(v.x, v.y), cvt_bf16x2(v.z, v.w));
    lo = make_uint2(cvt_bf16x2(v.x - hx, v.y - hy), cvt_bf16x2(v.z - hz, v.w - hw));
}

// ---------------------------------------------------------------------------
// edge index fetch with dtype branch
// ---------------------------------------------------------------------------
__device__ __forceinline__ int edge_idx(const void* ei_raw, size_t i) {
    if (g_is64) return (int)((const long long*)ei_raw)[i];
    return ((const int*)ei_raw)[i];
}

__global__ void detect_dtype_kernel(const int* __restrict__ ei32) {
    int all_zero = 1;
    for (int i = 0; i < 128; i++) {
        if (ei32[2 * i + 1] != 0) { all_zero = 0; break; }
    }
    g_is64 = all_zero;
}

// ---------------------------------------------------------------------------
// prep_x: split x fp32 -> bf16 hi/lo arrays (same [n*512+pos] layout)
// ---------------------------------------------------------------------------
__global__ __launch_bounds__(256)
void prep_x_kernel(const float* __restrict__ x) {
    size_t i = (size_t)blockIdx.x * blockDim.x + threadIdx.x;
    const size_t n4 = (size_t)N_NODES * ROW_F / 4;
    if (i >= n4) return;
    float4 v = __ldg((const float4*)x + i);
    uint2 hi, lo;
    split4(v, hi, lo);
    ((uint2*)g_xhi)[i] = hi;
    ((uint2*)g_xlo)[i] = lo;
}

// ---------------------------------------------------------------------------
// Weight prep: split stacked weights into bf16 hi + lo residual, [c][n][k]
// ---------------------------------------------------------------------------
__global__ void prep_weights_kernel(const float* __restrict__ Wsrel,
                                    const float* __restrict__ Wsroot,
                                    const float* __restrict__ Wvrel,
                                    const float* __restrict__ Wvroot) {
    int n = blockIdx.x;
    int c = blockIdx.y;
    int k = threadIdx.x;
    const float* root = (c == 0) ? Wsroot : Wvroot;
    const float* rel  = (c == 0) ? Wsrel  : Wvrel;
    float w = (k < 128) ? __ldg(root + n * 128 + k)
                        : __ldg(rel  + n * 128 + (k - 128));
    __nv_bfloat16 h = __float2bfloat16(w);
    float hf = __bfloat162float(h);
    __nv_bfloat16 l = __float2bfloat16(w - hf);
    size_t o = ((size_t)(c * 128 + n)) * 256 + k;
    g_Whi[o] = h;
    g_Wlo[o] = l;
}

// ---------------------------------------------------------------------------
// CSR build
// ---------------------------------------------------------------------------
__global__ void zero_cnt_kernel() {
    int i = blockIdx.x * blockDim.x + threadIdx.x;
    if (i < N_NODES) g_cnt[i] = 0;
}

__global__ __launch_bounds__(256)
void hist_kernel(const void* __restrict__ ei_raw) {
    int e = blockIdx.x * blockDim.x + threadIdx.x;
    if (e < E_EDGES) atomicAdd(&g_cnt[edge_idx(ei_raw, e)], 1);
}

// Warp-shuffle based single-block scan
__global__ __launch_bounds__(1024)
void scan_kernel() {
    __shared__ int wsum[32];
    __shared__ int carry_s;
    const int tid  = threadIdx.x;
    const int lane = tid & 31;
    const int w    = tid >> 5;
    if (tid == 0) carry_s = 0;
    __syncthreads();

    for (int base = 0; base < N_NODES; base += 1024) {
        int i = base + tid;
        int v = (i < N_NODES) ? g_cnt[i] : 0;
        int incl = v;
        #pragma unroll
        for (int d = 1; d < 32; d <<= 1) {
            int t = __shfl_up_sync(0xFFFFFFFFu, incl, d);
            if (lane >= d) incl += t;
        }
        if (lane == 31) wsum[w] = incl;
        __syncthreads();
        if (w == 0) {
            int s = wsum[lane];
            #pragma unroll
            for (int d = 1; d < 32; d <<= 1) {
                int t = __shfl_up_sync(0xFFFFFFFFu, s, d);
                if (lane >= d) s += t;
            }
            wsum[lane] = s;
        }
        __syncthreads();
        int wbase = (w > 0) ? wsum[w - 1] : 0;
        int excl = carry_s + wbase + incl - v;
        if (i < N_NODES) {
            g_off[i] = excl;
            g_cur[i] = excl;
        }
        int total = wsum[31];
        __syncthreads();
        if (tid == 0) carry_s += total;
        __syncthreads();
    }
    if (tid == 0) g_off[N_NODES] = carry_s;
}

__global__ __launch_bounds__(256)
void scatter_kernel(const void* __restrict__ ei_raw) {
    int e = blockIdx.x * blockDim.x + threadIdx.x;
    if (e < E_EDGES) {
        int row = edge_idx(ei_raw, e);
        int col = edge_idx(ei_raw, (size_t)E_EDGES + e);
        int pos = atomicAdd(&g_cur[row], 1);
        g_cols[pos] = col;
    }
}

// ---------------------------------------------------------------------------
// CSR aggregation (fp32 accumulate), writes split bf16 hi/lo
// ---------------------------------------------------------------------------
__global__ __launch_bounds__(256)
void csr_agg_kernel(const float* __restrict__ x) {
    int node = blockIdx.x * 2 + (threadIdx.x >> 7);
    int lane = threadIdx.x & 127;
    if (node >= N_NODES) return;

    int beg = __ldg(&g_off[node]);
    int end = __ldg(&g_off[node + 1]);

    float4 a0 = make_float4(0.f, 0.f, 0.f, 0.f);
    float4 a1 = make_float4(0.f, 0.f, 0.f, 0.f);
    float4 a2 = make_float4(0.f, 0.f, 0.f, 0.f);
    float4 a3 = make_float4(0.f, 0.f, 0.f, 0.f);
    int j = beg;
    for (; j + 3 < end; j += 4) {
        int c0 = __ldg(&g_cols[j]);
        int c1 = __ldg(&g_cols[j + 1]);
        int c2 = __ldg(&g_cols[j + 2]);
        int c3 = __ldg(&g_cols[j + 3]);
        float4 v0 = __ldg((const float4*)(x + (size_t)c0 * ROW_F) + lane);
        float4 v1 = __ldg((const float4*)(x + (size_t)c1 * ROW_F) + lane);
        float4 v2 = __ldg((const float4*)(x + (size_t)c2 * ROW_F) + lane);
        float4 v3 = __ldg((const float4*)(x + (size_t)c3 * ROW_F) + lane);
        a0.x += v0.x; a0.y += v0.y; a0.z += v0.z; a0.w += v0.w;
        a1.x += v1.x; a1.y += v1.y; a1.z += v1.z; a1.w += v1.w;
        a2.x += v2.x; a2.y += v2.y; a2.z += v2.z; a2.w += v2.w;
        a3.x += v3.x; a3.y += v3.y; a3.z += v3.z; a3.w += v3.w;
    }
    for (; j < end; j++) {
        int c0 = __ldg(&g_cols[j]);
        float4 v0 = __ldg((const float4*)(x + (size_t)c0 * ROW_F) + lane);
        a0.x += v0.x; a0.y += v0.y; a0.z += v0.z; a0.w += v0.w;
    }
    a0.x += a1.x + a2.x + a3.x;
    a0.y += a1.y + a2.y + a3.y;
    a0.z += a1.z + a2.z + a3.z;
    a0.w += a1.w + a2.w + a3.w;

    uint2 hi, lo;
    split4(a0, hi, lo);
    size_t o = (size_t)node * (ROW_F / 4) + lane;   // uint2 index
    ((uint2*)g_ahi)[o] = hi;
    ((uint2*)g_alo)[o] = lo;
}

// ---------------------------------------------------------------------------
// Transform: split-bf16 HMMA GEMM, fully cp.async double-buffered.
//   Block 128 nodes x 128 outs, 512 threads (16 warps, warp tile 32x32).
//   K=256 stacked [x | agg], chunked 4 x 64. Stage = A(hi,lo)+W(hi,lo) = 64KB,
//   2 stages = 128KB smem, 1 CTA/SM.
// ---------------------------------------------------------------------------
#define STAGE_SZ 65536
#define OFF_AHI  0
#define OFF_ALO  16384
#define OFF_WHI  32768
#define OFF_WLO  49152
#define SM_TOTAL (2 * STAGE_SZ)

__global__ __launch_bounds__(512, 1)
void transform_mma_kernel(const float* __restrict__ bsr,
                          float* __restrict__ out) {
    extern __shared__ char smem[];
    const uint32_t sb = smem_u32(smem);
    const int tid  = threadIdx.x;
    const int wid  = tid >> 5;
    const int lane = tid & 31;
    const int c      = blockIdx.y;
    const int node0  = blockIdx.x * 128;
    const int warp_m = (wid & 3) * 32;    // 4 warps along m
    const int warp_n = (wid >> 2) * 32;   // 4 warps along n

    float acc[2][4][4];
    #pragma unroll
    for (int mt = 0; mt < 2; mt++)
        #pragma unroll
        for (int j = 0; j < 4; j++)
            #pragma unroll
            for (int q = 0; q < 4; q++) acc[mt][j][q] = 0.f;

    // loader coords: 512 threads cover 64 rows x 8 units per iter, 2 iters
    const int lu = tid & 7;        // 16B unit within 128B row
    const int lr = tid >> 3;       // row 0..63

    // ldmatrix lane-address components
    const int a_row_l = lane & 15;
    const int a_koff  = (lane >> 4) << 4;
    const int b_row_l = ((lane >> 4) << 3) + (lane & 7);
    const int b_koff  = ((lane >> 3) & 1) << 4;

    const size_t wcbase = (size_t)c * 128 * 256;

    // ---- stage loader ----
    auto issue_chunk = [&](int kc, int st) {
        const uint32_t base = sb + st * STAGE_SZ;
        const __nv_bfloat16* shi = (kc < 2) ? g_xhi : g_ahi;
        const __nv_bfloat16* slo = (kc < 2) ? g_xlo : g_alo;
        const int koff = (kc & 1) * 64 + c * H_DIM;
        #pragma unroll
        for (int it = 0; it < 2; it++) {
            int row = lr + it * 64;
            uint32_t sw = SW128((uint32_t)(row * 128 + lu * 16));
            int node = node0 + row;
            if (node < N_NODES) {
                const __nv_bfloat16* ph = shi + (size_t)node * ROW_F + koff + lu * 8;
                const __nv_bfloat16* pl = slo + (size_t)node * ROW_F + koff + lu * 8;
                cp_async16(base + OFF_AHI + sw, ph);
                cp_async16(base + OFF_ALO + sw, pl);
            } else {
                uint4 z = make_uint4(0, 0, 0, 0);
                *(uint4*)(smem + st * STAGE_SZ + OFF_AHI + sw) = z;
                *(uint4*)(smem + st * STAGE_SZ + OFF_ALO + sw) = z;
            }
            const __nv_bfloat16* wh = g_Whi + wcbase + (size_t)row * 256 + kc * 64 + lu * 8;
            const __nv_bfloat16* wl = g_Wlo + wcbase + (size_t)row * 256 + kc * 64 + lu * 8;
            cp_async16(base + OFF_WHI + sw, wh);
            cp_async16(base + OFF_WLO + sw, wl);
        }
        cp_commit();
    };

    issue_chunk(0, 0);
    issue_chunk(1, 1);

    for (int kc = 0; kc < 4; kc++) {
        const int st = kc & 1;
        if (kc < 3) cp_wait<1>(); else cp_wait<0>();
        __syncthreads();

        const uint32_t base = sb + st * STAGE_SZ;
        #pragma unroll
        for (int ks = 0; ks < 4; ks++) {
            uint32_t ah[2][4], al[2][4];
            #pragma unroll
            for (int mt = 0; mt < 2; mt++) {
                uint32_t sw = SW128((uint32_t)((warp_m + mt * 16 + a_row_l) * 128
                                               + ks * 32 + a_koff));
                ldsm_x4(base + OFF_AHI + sw, ah[mt][0], ah[mt][1], ah[mt][2], ah[mt][3]);
                ldsm_x4(base + OFF_ALO + sw, al[mt][0], al[mt][1], al[mt][2], al[mt][3]);
            }
            #pragma unroll
            for (int np = 0; np < 2; np++) {
                uint32_t sw = SW128((uint32_t)((warp_n + np * 16 + b_row_l) * 128
                                               + ks * 32 + b_koff));
                uint32_t bh0, bh1, bh2, bh3, bl0, bl1, bl2, bl3;
                ldsm_x4(base + OFF_WHI + sw, bh0, bh1, bh2, bh3);
                ldsm_x4(base + OFF_WLO + sw, bl0, bl1, bl2, bl3);
                #pragma unroll
                for (int mt = 0; mt < 2; mt++) {
                    mma16816(acc[mt][np * 2 + 0], ah[mt], bh0, bh1);
                    mma16816(acc[mt][np * 2 + 0], al[mt], bh0, bh1);
                    mma16816(acc[mt][np * 2 + 0], ah[mt], bl0, bl1);
                    mma16816(acc[mt][np * 2 + 1], ah[mt], bh2, bh3);
                    mma16816(acc[mt][np * 2 + 1], al[mt], bh2, bh3);
                    mma16816(acc[mt][np * 2 + 1], ah[mt], bl2, bl3);
                }
            }
        }
        __syncthreads();
        if (kc + 2 < 4) issue_chunk(kc + 2, st);
    }

    // ---- epilogue ----
    const int erow = lane >> 2;
    const int ecol = (lane & 3) * 2;
    #pragma unroll
    for (int mt = 0; mt < 2; mt++) {
        #pragma unroll
        for (int j = 0; j < 4; j++) {
            int col = warp_n + j * 8 + ecol;
            float b0 = 0.f, b1 = 0.f;
            if (c == 0) { b0 = __ldg(bsr + col); b1 = __ldg(bsr + col + 1); }
            int r0 = node0 + warp_m + mt * 16 + erow;
            int r1 = r0 + 8;
            if (r0 < N_NODES) {
                float2 v = make_float2(acc[mt][j][0] + b0, acc[mt][j][1] + b1);
                *(float2*)(out + (size_t)r0 * ROW_F + (size_t)c * H_DIM + col) = v;
            }
            if (r1 < N_NODES) {
                float2 v = make_float2(acc[mt][j][2] + b0, acc[mt][j][3] + b1);
                *(float2*)(out + (size_t)r1 * ROW_F + (size_t)c * H_DIM + col) = v;
            }
        }
    }
}

// ---------------------------------------------------------------------------
// Launch
// ---------------------------------------------------------------------------
extern "C" void kernel_launch(void* const* d_in, const int* in_sizes, int n_in,
                              void* d_out, int out_size) {
    const float* x      = (const float*)d_in[0];
    const void*  ei     = d_in[1];
    const float* Wsrel  = (const float*)d_in[2];
    const float* Wsroot = (const float*)d_in[3];
    const float* bsr    = (const float*)d_in[4];
    const float* Wvrel  = (const float*)d_in[5];
    const float* Wvroot = (const float*)d_in[6];
    float*       out    = (float*)d_out;

    cudaFuncSetAttribute(transform_mma_kernel,
                         cudaFuncAttributeMaxDynamicSharedMemorySize, SM_TOTAL);

    // Phase 0: dtype detect + weight split + x split
    detect_dtype_kernel<<<1, 1>>>((const int*)ei);
    {
        dim3 grid(128, 4);
        prep_weights_kernel<<<grid, 256>>>(Wsrel, Wsroot, Wvrel, Wvroot);
    }
    {
        const size_t n4 = (size_t)N_NODES * ROW_F / 4;
        prep_x_kernel<<<(int)((n4 + 255) / 256), 256>>>(x);
    }

    // Phase 1: CSR build
    zero_cnt_kernel<<<(N_NODES + 255) / 256, 256>>>();
    hist_kernel<<<(E_EDGES + 255) / 256, 256>>>(ei);
    scan_kernel<<<1, 1024>>>();
    scatter_kernel<<<(E_EDGES + 255) / 256, 256>>>(ei);

    // Phase 2: CSR aggregation (fp32 gather, split-bf16 output)
    csr_agg_kernel<<<(N_NODES + 1) / 2, 256>>>(x);

    // Phase 3: transform (split-bf16 HMMA, double-buffered cp.async)
    {
        dim3 grid((N_NODES + 127) / 128, 4);
        transform_mma_kernel<<<grid, 512, SM_TOTAL>>>(bsr, out);
    }
}

// round 9
// speedup vs baseline: 1.3113x; 1.2459x over previous
#include <cuda_runtime.h>
#include <cuda_bf16.h>
#include <cuda_fp16.h>
#include <cstdint>

#define N_NODES 50000
#define E_EDGES 500000
#define H_DIM   128
#define ROW_F   512          // 4 channels * 128 floats per node

// ---------------------------------------------------------------------------
// Global scratch
// ---------------------------------------------------------------------------
__device__ __nv_bfloat16 g_xhi[(size_t)N_NODES * ROW_F];
__device__ __nv_bfloat16 g_xlo[(size_t)N_NODES * ROW_F];
__device__ __half        g_xh [(size_t)N_NODES * ROW_F];   // fp16 x for gather
__device__ __nv_bfloat16 g_ahi[(size_t)N_NODES * ROW_F];
__device__ __nv_bfloat16 g_alo[(size_t)N_NODES * ROW_F];
__device__ __nv_bfloat16 g_Whi[4 * 128 * 256];   // [c][n][k] hi halves
__device__ __nv_bfloat16 g_Wlo[4 * 128 * 256];   // [c][n][k] lo residuals
__device__ int g_is64;
__device__ int g_cnt[N_NODES];
__device__ int g_off[N_NODES + 1];
__device__ int g_cur[N_NODES];
__device__ int g_cols[E_EDGES];

// ---------------------------------------------------------------------------
// helpers
// ---------------------------------------------------------------------------
__device__ __forceinline__ uint32_t smem_u32(const void* p) {
    uint32_t a;
    asm("{ .reg .u64 t; cvta.to.shared.u64 t, %1; cvt.u32.u64 %0, t; }"
        : "=r"(a) : "l"(p));
    return a;
}

// pack two f32 into bf16x2 (lo arg -> low half, hi arg -> high half)
__device__ __forceinline__ uint32_t cvt_bf16x2(float lo, float hi) {
    uint32_t r;
    asm("cvt.rn.bf16x2.f32 %0, %1, %2;" : "=r"(r) : "f"(hi), "f"(lo));
    return r;
}

#define SW128(o) ((o) ^ (((o) >> 3) & 0x70))

__device__ __forceinline__ void ldsm_x4(uint32_t addr, uint32_t& r0, uint32_t& r1,
                                        uint32_t& r2, uint32_t& r3) {
    asm volatile("ldmatrix.sync.aligned.m8n8.x4.shared.b16 {%0,%1,%2,%3}, [%4];"
                 : "=r"(r0), "=r"(r1), "=r"(r2), "=r"(r3) : "r"(addr));
}

__device__ __forceinline__ void mma16816(float* c, const uint32_t* a,
                                         uint32_t b0, uint32_t b1) {
    asm volatile(
        "mma.sync.aligned.m16n8k16.row.col.f32.bf16.bf16.f32 "
        "{%0,%1,%2,%3}, {%4,%5,%6,%7}, {%8,%9}, {%0,%1,%2,%3};"
        : "+f"(c[0]), "+f"(c[1]), "+f"(c[2]), "+f"(c[3])
        : "r"(a[0]), "r"(a[1]), "r"(a[2]), "r"(a[3]), "r"(b0), "r"(b1));
}

__device__ __forceinline__ void cp_async16(uint32_t smem_addr, const void* gptr) {
    asm volatile("cp.async.cg.shared.global [%0], [%1], 16;"
                 :: "r"(smem_addr), "l"(gptr) : "memory");
}
__device__ __forceinline__ void cp_commit() {
    asm volatile("cp.async.commit_group;" ::: "memory");
}
template <int N>
__device__ __forceinline__ void cp_wait() {
    asm volatile("cp.async.wait_group %0;" :: "n"(N) : "memory");
}

// split a float4 into hi/lo bf16x2 pairs
__device__ __forceinline__ void split4(float4 v, uint2& hi, uint2& lo) {
    float hx = __bfloat162float(__float2bfloat16(v.x));
    float hy = __bfloat162float(__float2bfloat16(v.y));
    float hz = __bfloat162float(__float2bfloat16(v.z));
    float hw = __bfloat162float(__float2bfloat16(v.w));
    hi = make_uint2(cvt_bf16x2(v.x, v.y), cvt_bf16x2(v.z, v.w));
    lo = make_uint2(cvt_bf16x2(v.x - hx, v.y - hy), cvt_bf16x2(v.z - hz, v.w - hw));
}

// accumulate 8 fp16 values (packed in uint4) into float acc[8]
__device__ __forceinline__ void add8(float* a, uint4 v) {
    float2 f;
    f = __half22float2(*(__half2*)&v.x); a[0] += f.x; a[1] += f.y;
    f = __half22float2(*(__half2*)&v.y); a[2] += f.x; a[3] += f.y;
    f = __half22float2(*(__half2*)&v.z); a[4] += f.x; a[5] += f.y;
    f = __half22float2(*(__half2*)&v.w); a[6] += f.x; a[7] += f.y;
}

// ---------------------------------------------------------------------------
// edge index fetch with dtype branch
// ---------------------------------------------------------------------------
__device__ __forceinline__ int edge_idx(const void* ei_raw, size_t i) {
    if (g_is64) return (int)((const long long*)ei_raw)[i];
    return ((const int*)ei_raw)[i];
}

__global__ void detect_dtype_kernel(const int* __restrict__ ei32) {
    int all_zero = 1;
    for (int i = 0; i < 128; i++) {
        if (ei32[2 * i + 1] != 0) { all_zero = 0; break; }
    }
    g_is64 = all_zero;
}

// ---------------------------------------------------------------------------
// prep_x: split x fp32 -> bf16 hi/lo arrays + fp16 copy for gathering
// ---------------------------------------------------------------------------
__global__ __launch_bounds__(256)
void prep_x_kernel(const float* __restrict__ x) {
    size_t i = (size_t)blockIdx.x * blockDim.x + threadIdx.x;
    const size_t n4 = (size_t)N_NODES * ROW_F / 4;
    if (i >= n4) return;
    float4 v = __ldg((const float4*)x + i);
    uint2 hi, lo;
    split4(v, hi, lo);
    ((uint2*)g_xhi)[i] = hi;
    ((uint2*)g_xlo)[i] = lo;
    __half2 h0 = __floats2half2_rn(v.x, v.y);
    __half2 h1 = __floats2half2_rn(v.z, v.w);
    uint2 hp;
    hp.x = *(uint32_t*)&h0;
    hp.y = *(uint32_t*)&h1;
    ((uint2*)g_xh)[i] = hp;
}

// ---------------------------------------------------------------------------
// Weight prep: split stacked weights into bf16 hi + lo residual, [c][n][k]
// ---------------------------------------------------------------------------
__global__ void prep_weights_kernel(const float* __restrict__ Wsrel,
                                    const float* __restrict__ Wsroot,
                                    const float* __restrict__ Wvrel,
                                    const float* __restrict__ Wvroot) {
    int n = blockIdx.x;
    int c = blockIdx.y;
    int k = threadIdx.x;
    const float* root = (c == 0) ? Wsroot : Wvroot;
    const float* rel  = (c == 0) ? Wsrel  : Wvrel;
    float w = (k < 128) ? __ldg(root + n * 128 + k)
                        : __ldg(rel  + n * 128 + (k - 128));
    __nv_bfloat16 h = __float2bfloat16(w);
    float hf = __bfloat162float(h);
    __nv_bfloat16 l = __float2bfloat16(w - hf);
    size_t o = ((size_t)(c * 128 + n)) * 256 + k;
    g_Whi[o] = h;
    g_Wlo[o] = l;
}

// ---------------------------------------------------------------------------
// CSR build
// ---------------------------------------------------------------------------
__global__ void zero_cnt_kernel() {
    int i = blockIdx.x * blockDim.x + threadIdx.x;
    if (i < N_NODES) g_cnt[i] = 0;
}

__global__ __launch_bounds__(256)
void hist_kernel(const void* __restrict__ ei_raw) {
    int e = blockIdx.x * blockDim.x + threadIdx.x;
    if (e < E_EDGES) atomicAdd(&g_cnt[edge_idx(ei_raw, e)], 1);
}

// Warp-shuffle based single-block scan
__global__ __launch_bounds__(1024)
void scan_kernel() {
    __shared__ int wsum[32];
    __shared__ int carry_s;
    const int tid  = threadIdx.x;
    const int lane = tid & 31;
    const int w    = tid >> 5;
    if (tid == 0) carry_s = 0;
    __syncthreads();

    for (int base = 0; base < N_NODES; base += 1024) {
        int i = base + tid;
        int v = (i < N_NODES) ? g_cnt[i] : 0;
        int incl = v;
        #pragma unroll
        for (int d = 1; d < 32; d <<= 1) {
            int t = __shfl_up_sync(0xFFFFFFFFu, incl, d);
            if (lane >= d) incl += t;
        }
        if (lane == 31) wsum[w] = incl;
        __syncthreads();
        if (w == 0) {
            int s = wsum[lane];
            #pragma unroll
            for (int d = 1; d < 32; d <<= 1) {
                int t = __shfl_up_sync(0xFFFFFFFFu, s, d);
                if (lane >= d) s += t;
            }
            wsum[lane] = s;
        }
        __syncthreads();
        int wbase = (w > 0) ? wsum[w - 1] : 0;
        int excl = carry_s + wbase + incl - v;
        if (i < N_NODES) {
            g_off[i] = excl;
            g_cur[i] = excl;
        }
        int total = wsum[31];
        __syncthreads();
        if (tid == 0) carry_s += total;
        __syncthreads();
    }
    if (tid == 0) g_off[N_NODES] = carry_s;
}

__global__ __launch_bounds__(256)
void scatter_kernel(const void* __restrict__ ei_raw) {
    int e = blockIdx.x * blockDim.x + threadIdx.x;
    if (e < E_EDGES) {
        int row = edge_idx(ei_raw, e);
        int col = edge_idx(ei_raw, (size_t)E_EDGES + e);
        int pos = atomicAdd(&g_cur[row], 1);
        g_cols[pos] = col;
    }
}

// ---------------------------------------------------------------------------
// CSR aggregation: gather fp16 rows (512B/edge), fp32 accumulate,
// write split bf16 hi/lo. 64 lanes per node, 4 nodes per 256-thread block.
// ---------------------------------------------------------------------------
__global__ __launch_bounds__(256)
void csr_agg_kernel() {
    int node = blockIdx.x * 4 + (threadIdx.x >> 6);
    int lane = threadIdx.x & 63;
    if (node >= N_NODES) return;

    int beg = __ldg(&g_off[node]);
    int end = __ldg(&g_off[node + 1]);

    float acc[8];
    #pragma unroll
    for (int q = 0; q < 8; q++) acc[q] = 0.f;

    int j = beg;
    for (; j + 1 < end; j += 2) {
        int c0 = __ldg(&g_cols[j]);
        int c1 = __ldg(&g_cols[j + 1]);
        uint4 v0 = __ldg((const uint4*)(g_xh + (size_t)c0 * ROW_F) + lane);
        uint4 v1 = __ldg((const uint4*)(g_xh + (size_t)c1 * ROW_F) + lane);
        add8(acc, v0);
        add8(acc, v1);
    }
    if (j < end) {
        int c0 = __ldg(&g_cols[j]);
        uint4 v0 = __ldg((const uint4*)(g_xh + (size_t)c0 * ROW_F) + lane);
        add8(acc, v0);
    }

    uint2 hi, lo;
    size_t o = (size_t)node * (ROW_F / 4) + lane * 2;   // uint2 index (4 elems each)
    split4(make_float4(acc[0], acc[1], acc[2], acc[3]), hi, lo);
    ((uint2*)g_ahi)[o] = hi;
    ((uint2*)g_alo)[o] = lo;
    split4(make_float4(acc[4], acc[5], acc[6], acc[7]), hi, lo);
    ((uint2*)g_ahi)[o + 1] = hi;
    ((uint2*)g_alo)[o + 1] = lo;
}

// ---------------------------------------------------------------------------
// Transform: split-bf16 HMMA GEMM, fully cp.async double-buffered.
//   Block 128 nodes x 128 outs, 512 threads (16 warps, warp tile 32x32).
// ---------------------------------------------------------------------------
#define STAGE_SZ 65536
#define OFF_AHI  0
#define OFF_ALO  16384
#define OFF_WHI  32768
#define OFF_WLO  49152
#define SM_TOTAL (2 * STAGE_SZ)

__global__ __launch_bounds__(512, 1)
void transform_mma_kernel(const float* __restrict__ bsr,
                          float* __restrict__ out) {
    extern __shared__ char smem[];
    const uint32_t sb = smem_u32(smem);
    const int tid  = threadIdx.x;
    const int wid  = tid >> 5;
    const int lane = tid & 31;
    const int c      = blockIdx.y;
    const int node0  = blockIdx.x * 128;
    const int warp_m = (wid & 3) * 32;    // 4 warps along m
    const int warp_n = (wid >> 2) * 32;   // 4 warps along n

    float acc[2][4][4];
    #pragma unroll
    for (int mt = 0; mt < 2; mt++)
        #pragma unroll
        for (int j = 0; j < 4; j++)
            #pragma unroll
            for (int q = 0; q < 4; q++) acc[mt][j][q] = 0.f;

    // loader coords: 512 threads cover 64 rows x 8 units per iter, 2 iters
    const int lu = tid & 7;        // 16B unit within 128B row
    const int lr = tid >> 3;       // row 0..63

    // ldmatrix lane-address components
    const int a_row_l = lane & 15;
    const int a_koff  = (lane >> 4) << 4;
    const int b_row_l = ((lane >> 4) << 3) + (lane & 7);
    const int b_koff  = ((lane >> 3) & 1) << 4;

    const size_t wcbase = (size_t)c * 128 * 256;

    auto issue_chunk = [&](int kc, int st) {
        const uint32_t base = sb + st * STAGE_SZ;
        const __nv_bfloat16* shi = (kc < 2) ? g_xhi : g_ahi;
        const __nv_bfloat16* slo = (kc < 2) ? g_xlo : g_alo;
        const int koff = (kc & 1) * 64 + c * H_DIM;
        #pragma unroll
        for (int it = 0; it < 2; it++) {
            int row = lr + it * 64;
            uint32_t sw = SW128((uint32_t)(row * 128 + lu * 16));
            int node = node0 + row;
            if (node < N_NODES) {
                const __nv_bfloat16* ph = shi + (size_t)node * ROW_F + koff + lu * 8;
                const __nv_bfloat16* pl = slo + (size_t)node * ROW_F + koff + lu * 8;
                cp_async16(base + OFF_AHI + sw, ph);
                cp_async16(base + OFF_ALO + sw, pl);
            } else {
                uint4 z = make_uint4(0, 0, 0, 0);
                *(uint4*)(smem + st * STAGE_SZ + OFF_AHI + sw) = z;
                *(uint4*)(smem + st * STAGE_SZ + OFF_ALO + sw) = z;
            }
            const __nv_bfloat16* wh = g_Whi + wcbase + (size_t)row * 256 + kc * 64 + lu * 8;
            const __nv_bfloat16* wl = g_Wlo + wcbase + (size_t)row * 256 + kc * 64 + lu * 8;
            cp_async16(base + OFF_WHI + sw, wh);
            cp_async16(base + OFF_WLO + sw, wl);
        }
        cp_commit();
    };

    issue_chunk(0, 0);
    issue_chunk(1, 1);

    for (int kc = 0; kc < 4; kc++) {
        const int st = kc & 1;
        if (kc < 3) cp_wait<1>(); else cp_wait<0>();
        __syncthreads();

        const uint32_t base = sb + st * STAGE_SZ;
        #pragma unroll
        for (int ks = 0; ks < 4; ks++) {
            uint32_t ah[2][4], al[2][4];
            #pragma unroll
            for (int mt = 0; mt < 2; mt++) {
                uint32_t sw = SW128((uint32_t)((warp_m + mt * 16 + a_row_l) * 128
                                               + ks * 32 + a_koff));
                ldsm_x4(base + OFF_AHI + sw, ah[mt][0], ah[mt][1], ah[mt][2], ah[mt][3]);
                ldsm_x4(base + OFF_ALO + sw, al[mt][0], al[mt][1], al[mt][2], al[mt][3]);
            }
            #pragma unroll
            for (int np = 0; np < 2; np++) {
                uint32_t sw = SW128((uint32_t)((warp_n + np * 16 + b_row_l) * 128
                                               + ks * 32 + b_koff));
                uint32_t bh0, bh1, bh2, bh3, bl0, bl1, bl2, bl3;
                ldsm_x4(base + OFF_WHI + sw, bh0, bh1, bh2, bh3);
                ldsm_x4(base + OFF_WLO + sw, bl0, bl1, bl2, bl3);
                #pragma unroll
                for (int mt = 0; mt < 2; mt++) {
                    mma16816(acc[mt][np * 2 + 0], ah[mt], bh0, bh1);
                    mma16816(acc[mt][np * 2 + 0], al[mt], bh0, bh1);
                    mma16816(acc[mt][np * 2 + 0], ah[mt], bl0, bl1);
                    mma16816(acc[mt][np * 2 + 1], ah[mt], bh2, bh3);
                    mma16816(acc[mt][np * 2 + 1], al[mt], bh2, bh3);
                    mma16816(acc[mt][np * 2 + 1], ah[mt], bl2, bl3);
                }
            }
        }
        __syncthreads();
        if (kc + 2 < 4) issue_chunk(kc + 2, st);
    }

    // ---- epilogue ----
    const int erow = lane >> 2;
    const int ecol = (lane & 3) * 2;
    #pragma unroll
    for (int mt = 0; mt < 2; mt++) {
        #pragma unroll
        for (int j = 0; j < 4; j++) {
            int col = warp_n + j * 8 + ecol;
            float b0 = 0.f, b1 = 0.f;
            if (c == 0) { b0 = __ldg(bsr + col); b1 = __ldg(bsr + col + 1); }
            int r0 = node0 + warp_m + mt * 16 + erow;
            int r1 = r0 + 8;
            if (r0 < N_NODES) {
                float2 v = make_float2(acc[mt][j][0] + b0, acc[mt][j][1] + b1);
                *(float2*)(out + (size_t)r0 * ROW_F + (size_t)c * H_DIM + col) = v;
            }
            if (r1 < N_NODES) {
                float2 v = make_float2(acc[mt][j][2] + b0, acc[mt][j][3] + b1);
                *(float2*)(out + (size_t)r1 * ROW_F + (size_t)c * H_DIM + col) = v;
            }
        }
    }
}

// ---------------------------------------------------------------------------
// Launch
// ---------------------------------------------------------------------------
extern "C" void kernel_launch(void* const* d_in, const int* in_sizes, int n_in,
                              void* d_out, int out_size) {
    const float* x      = (const float*)d_in[0];
    const void*  ei     = d_in[1];
    const float* Wsrel  = (const float*)d_in[2];
    const float* Wsroot = (const float*)d_in[3];
    const float* bsr    = (const float*)d_in[4];
    const float* Wvrel  = (const float*)d_in[5];
    const float* Wvroot = (const float*)d_in[6];
    float*       out    = (float*)d_out;

    cudaFuncSetAttribute(transform_mma_kernel,
                         cudaFuncAttributeMaxDynamicSharedMemorySize, SM_TOTAL);

    // Phase 0: dtype detect + weight split + x split/fp16
    detect_dtype_kernel<<<1, 1>>>((const int*)ei);
    {
        dim3 grid(128, 4);
        prep_weights_kernel<<<grid, 256>>>(Wsrel, Wsroot, Wvrel, Wvroot);
    }
    {
        const size_t n4 = (size_t)N_NODES * ROW_F / 4;
        prep_x_kernel<<<(int)((n4 + 255) / 256), 256>>>(x);
    }

    // Phase 1: CSR build
    zero_cnt_kernel<<<(N_NODES + 255) / 256, 256>>>();
    hist_kernel<<<(E_EDGES + 255) / 256, 256>>>(ei);
    scan_kernel<<<1, 1024>>>();
    scatter_kernel<<<(E_EDGES + 255) / 256, 256>>>(ei);

    // Phase 2: CSR aggregation (fp16 gather, fp32 accumulate, split-bf16 out)
    csr_agg_kernel<<<(N_NODES + 3) / 4, 256>>>();

    // Phase 3: transform (split-bf16 HMMA, double-buffered cp.async)
    {
        dim3 grid((N_NODES + 127) / 128, 4);
        transform_mma_kernel<<<grid, 512, SM_TOTAL>>>(bsr, out);
    }
}

// round 10
// speedup vs baseline: 1.8605x; 1.4188x over previous
#include <cuda_runtime.h>
#include <cuda_fp16.h>
#include <cstdint>

#define N_NODES 50000
#define E_EDGES 500000
#define H_DIM   128
#define ROW_F   512          // 4 channels * 128 floats per node

// ---------------------------------------------------------------------------
// Global scratch
// ---------------------------------------------------------------------------
__device__ __half g_xh[(size_t)N_NODES * ROW_F];   // fp16 x
__device__ __half g_ah[(size_t)N_NODES * ROW_F];   // fp16 agg
__device__ __half g_Wh[4 * 128 * 256];             // [c][n][k] fp16 stacked W
__device__ int g_is64;
__device__ int g_cnt[N_NODES];
__device__ int g_off[N_NODES + 1];
__device__ int g_cur[N_NODES];
__device__ int g_cols[E_EDGES];

// ---------------------------------------------------------------------------
// helpers
// ---------------------------------------------------------------------------
__device__ __forceinline__ uint32_t smem_u32(const void* p) {
    uint32_t a;
    asm("{ .reg .u64 t; cvta.to.shared.u64 t, %1; cvt.u32.u64 %0, t; }"
        : "=r"(a) : "l"(p));
    return a;
}

#define SW128(o) ((o) ^ (((o) >> 3) & 0x70))

__device__ __forceinline__ void ldsm_x4(uint32_t addr, uint32_t& r0, uint32_t& r1,
                                        uint32_t& r2, uint32_t& r3) {
    asm volatile("ldmatrix.sync.aligned.m8n8.x4.shared.b16 {%0,%1,%2,%3}, [%4];"
                 : "=r"(r0), "=r"(r1), "=r"(r2), "=r"(r3) : "r"(addr));
}

__device__ __forceinline__ void mma16816h(float* c, const uint32_t* a,
                                          uint32_t b0, uint32_t b1) {
    asm volatile(
        "mma.sync.aligned.m16n8k16.row.col.f32.f16.f16.f32 "
        "{%0,%1,%2,%3}, {%4,%5,%6,%7}, {%8,%9}, {%0,%1,%2,%3};"
        : "+f"(c[0]), "+f"(c[1]), "+f"(c[2]), "+f"(c[3])
        : "r"(a[0]), "r"(a[1]), "r"(a[2]), "r"(a[3]), "r"(b0), "r"(b1));
}

__device__ __forceinline__ void cp_async16(uint32_t smem_addr, const void* gptr) {
    asm volatile("cp.async.cg.shared.global [%0], [%1], 16;"
                 :: "r"(smem_addr), "l"(gptr) : "memory");
}
__device__ __forceinline__ void cp_commit() {
    asm volatile("cp.async.commit_group;" ::: "memory");
}
template <int N>
__device__ __forceinline__ void cp_wait() {
    asm volatile("cp.async.wait_group %0;" :: "n"(N) : "memory");
}

// accumulate 8 fp16 values (packed in uint4) into float acc[8]
__device__ __forceinline__ void add8(float* a, uint4 v) {
    float2 f;
    f = __half22float2(*(__half2*)&v.x); a[0] += f.x; a[1] += f.y;
    f = __half22float2(*(__half2*)&v.y); a[2] += f.x; a[3] += f.y;
    f = __half22float2(*(__half2*)&v.z); a[4] += f.x; a[5] += f.y;
    f = __half22float2(*(__half2*)&v.w); a[6] += f.x; a[7] += f.y;
}

// ---------------------------------------------------------------------------
// edge index fetch with dtype branch
// ---------------------------------------------------------------------------
__device__ __forceinline__ int edge_idx(const void* ei_raw, size_t i) {
    if (g_is64) return (int)((const long long*)ei_raw)[i];
    return ((const int*)ei_raw)[i];
}

__global__ void detect_dtype_kernel(const int* __restrict__ ei32) {
    int all_zero = 1;
    for (int i = 0; i < 128; i++) {
        if (ei32[2 * i + 1] != 0) { all_zero = 0; break; }
    }
    g_is64 = all_zero;
}

// ---------------------------------------------------------------------------
// prep_x: x fp32 -> fp16
// ---------------------------------------------------------------------------
__global__ __launch_bounds__(256)
void prep_x_kernel(const float* __restrict__ x) {
    size_t i = (size_t)blockIdx.x * blockDim.x + threadIdx.x;
    const size_t n4 = (size_t)N_NODES * ROW_F / 4;
    if (i >= n4) return;
    float4 v = __ldg((const float4*)x + i);
    __half2 h0 = __floats2half2_rn(v.x, v.y);
    __half2 h1 = __floats2half2_rn(v.z, v.w);
    uint2 hp;
    hp.x = *(uint32_t*)&h0;
    hp.y = *(uint32_t*)&h1;
    ((uint2*)g_xh)[i] = hp;
}

// ---------------------------------------------------------------------------
// Weight prep: stacked fp16 weights, [c][n][k]; k<128 root, k>=128 rel
// ---------------------------------------------------------------------------
__global__ void prep_weights_kernel(const float* __restrict__ Wsrel,
                                    const float* __restrict__ Wsroot,
                                    const float* __restrict__ Wvrel,
                                    const float* __restrict__ Wvroot) {
    int n = blockIdx.x;
    int c = blockIdx.y;
    int k = threadIdx.x;
    const float* root = (c == 0) ? Wsroot : Wvroot;
    const float* rel  = (c == 0) ? Wsrel  : Wvrel;
    float w = (k < 128) ? __ldg(root + n * 128 + k)
                        : __ldg(rel  + n * 128 + (k - 128));
    g_Wh[((size_t)(c * 128 + n)) * 256 + k] = __float2half_rn(w);
}

// ---------------------------------------------------------------------------
// CSR build
// ---------------------------------------------------------------------------
__global__ void zero_cnt_kernel() {
    int i = blockIdx.x * blockDim.x + threadIdx.x;
    if (i < N_NODES) g_cnt[i] = 0;
}

__global__ __launch_bounds__(256)
void hist_kernel(const void* __restrict__ ei_raw) {
    int e = blockIdx.x * blockDim.x + threadIdx.x;
    if (e < E_EDGES) atomicAdd(&g_cnt[edge_idx(ei_raw, e)], 1);
}

__global__ __launch_bounds__(1024)
void scan_kernel() {
    __shared__ int wsum[32];
    __shared__ int carry_s;
    const int tid  = threadIdx.x;
    const int lane = tid & 31;
    const int w    = tid >> 5;
    if (tid == 0) carry_s = 0;
    __syncthreads();

    for (int base = 0; base < N_NODES; base += 1024) {
        int i = base + tid;
        int v = (i < N_NODES) ? g_cnt[i] : 0;
        int incl = v;
        #pragma unroll
        for (int d = 1; d < 32; d <<= 1) {
            int t = __shfl_up_sync(0xFFFFFFFFu, incl, d);
            if (lane >= d) incl += t;
        }
        if (lane == 31) wsum[w] = incl;
        __syncthreads();
        if (w == 0) {
            int s = wsum[lane];
            #pragma unroll
            for (int d = 1; d < 32; d <<= 1) {
                int t = __shfl_up_sync(0xFFFFFFFFu, s, d);
                if (lane >= d) s += t;
            }
            wsum[lane] = s;
        }
        __syncthreads();
        int wbase = (w > 0) ? wsum[w - 1] : 0;
        int excl = carry_s + wbase + incl - v;
        if (i < N_NODES) {
            g_off[i] = excl;
            g_cur[i] = excl;
        }
        int total = wsum[31];
        __syncthreads();
        if (tid == 0) carry_s += total;
        __syncthreads();
    }
    if (tid == 0) g_off[N_NODES] = carry_s;
}

__global__ __launch_bounds__(256)
void scatter_kernel(const void* __restrict__ ei_raw) {
    int e = blockIdx.x * blockDim.x + threadIdx.x;
    if (e < E_EDGES) {
        int row = edge_idx(ei_raw, e);
        int col = edge_idx(ei_raw, (size_t)E_EDGES + e);
        int pos = atomicAdd(&g_cur[row], 1);
        g_cols[pos] = col;
    }
}

// ---------------------------------------------------------------------------
// CSR aggregation: gather fp16 rows (512B/edge), fp32 accumulate, fp16 out.
// 64 lanes per node, 4 nodes per 256-thread block.
// ---------------------------------------------------------------------------
__global__ __launch_bounds__(256)
void csr_agg_kernel() {
    int node = blockIdx.x * 4 + (threadIdx.x >> 6);
    int lane = threadIdx.x & 63;
    if (node >= N_NODES) return;

    int beg = __ldg(&g_off[node]);
    int end = __ldg(&g_off[node + 1]);

    float acc[8];
    #pragma unroll
    for (int q = 0; q < 8; q++) acc[q] = 0.f;

    int j = beg;
    for (; j + 1 < end; j += 2) {
        int c0 = __ldg(&g_cols[j]);
        int c1 = __ldg(&g_cols[j + 1]);
        uint4 v0 = __ldg((const uint4*)(g_xh + (size_t)c0 * ROW_F) + lane);
        uint4 v1 = __ldg((const uint4*)(g_xh + (size_t)c1 * ROW_F) + lane);
        add8(acc, v0);
        add8(acc, v1);
    }
    if (j < end) {
        int c0 = __ldg(&g_cols[j]);
        uint4 v0 = __ldg((const uint4*)(g_xh + (size_t)c0 * ROW_F) + lane);
        add8(acc, v0);
    }

    __half2 h0 = __floats2half2_rn(acc[0], acc[1]);
    __half2 h1 = __floats2half2_rn(acc[2], acc[3]);
    __half2 h2 = __floats2half2_rn(acc[4], acc[5]);
    __half2 h3 = __floats2half2_rn(acc[6], acc[7]);
    uint4 o;
    o.x = *(uint32_t*)&h0; o.y = *(uint32_t*)&h1;
    o.z = *(uint32_t*)&h2; o.w = *(uint32_t*)&h3;
    ((uint4*)(g_ah + (size_t)node * ROW_F))[lane] = o;
}

// ---------------------------------------------------------------------------
// Transform: fp16 HMMA GEMM, 3-stage cp.async pipeline.
//   Block 128 nodes x 128 outs, 512 threads (16 warps, warp tile 32x32).
//   K=256 stacked [x | agg], chunked 4 x 64. Stage = A + W = 32 KB.
// ---------------------------------------------------------------------------
#define NSTAGE   3
#define STAGE_SZ 32768
#define OFF_A    0
#define OFF_W    16384
#define SM_TOTAL (NSTAGE * STAGE_SZ)   // 98304

__global__ __launch_bounds__(512, 1)
void transform_mma_kernel(const float* __restrict__ bsr,
                          float* __restrict__ out) {
    extern __shared__ char smem[];
    const uint32_t sb = smem_u32(smem);
    const int tid  = threadIdx.x;
    const int wid  = tid >> 5;
    const int lane = tid & 31;
    const int c      = blockIdx.y;
    const int node0  = blockIdx.x * 128;
    const int warp_m = (wid & 3) * 32;    // 4 warps along m
    const int warp_n = (wid >> 2) * 32;   // 4 warps along n

    float acc[2][4][4];
    #pragma unroll
    for (int mt = 0; mt < 2; mt++)
        #pragma unroll
        for (int j = 0; j < 4; j++)
            #pragma unroll
            for (int q = 0; q < 4; q++) acc[mt][j][q] = 0.f;

    // loader coords: 512 threads cover 64 rows x 8 units per iter, 2 iters
    const int lu = tid & 7;        // 16B unit within 128B row
    const int lr = tid >> 3;       // row 0..63

    // ldmatrix lane-address components
    const int a_row_l = lane & 15;
    const int a_koff  = (lane >> 4) << 4;
    const int b_row_l = ((lane >> 4) << 3) + (lane & 7);
    const int b_koff  = ((lane >> 3) & 1) << 4;

    const size_t wcbase = (size_t)c * 128 * 256;

    auto issue_chunk = [&](int kc, int st) {
        const uint32_t base = sb + st * STAGE_SZ;
        const __half* src = (kc < 2) ? g_xh : g_ah;
        const int koff = (kc & 1) * 64 + c * H_DIM;
        #pragma unroll
        for (int it = 0; it < 2; it++) {
            int row = lr + it * 64;
            uint32_t sw = SW128((uint32_t)(row * 128 + lu * 16));
            int node = node0 + row;
            if (node < N_NODES) {
                cp_async16(base + OFF_A + sw,
                           src + (size_t)node * ROW_F + koff + lu * 8);
            } else {
                uint4 z = make_uint4(0, 0, 0, 0);
                *(uint4*)(smem + st * STAGE_SZ + OFF_A + sw) = z;
            }
            cp_async16(base + OFF_W + sw,
                       g_Wh + wcbase + (size_t)row * 256 + kc * 64 + lu * 8);
        }
        cp_commit();
    };

    issue_chunk(0, 0);
    issue_chunk(1, 1);
    issue_chunk(2, 2);

    for (int kc = 0; kc < 4; kc++) {
        const int st = kc % NSTAGE;
        if (kc == 0)      cp_wait<2>();
        else if (kc == 1) cp_wait<2>();
        else if (kc == 2) cp_wait<1>();
        else              cp_wait<0>();
        __syncthreads();

        const uint32_t base = sb + st * STAGE_SZ;
        #pragma unroll
        for (int ks = 0; ks < 4; ks++) {
            uint32_t ah[2][4];
            #pragma unroll
            for (int mt = 0; mt < 2; mt++) {
                uint32_t sw = SW128((uint32_t)((warp_m + mt * 16 + a_row_l) * 128
                                               + ks * 32 + a_koff));
                ldsm_x4(base + OFF_A + sw, ah[mt][0], ah[mt][1], ah[mt][2], ah[mt][3]);
            }
            #pragma unroll
            for (int np = 0; np < 2; np++) {
                uint32_t sw = SW128((uint32_t)((warp_n + np * 16 + b_row_l) * 128
                                               + ks * 32 + b_koff));
                uint32_t bh0, bh1, bh2, bh3;
                ldsm_x4(base + OFF_W + sw, bh0, bh1, bh2, bh3);
                #pragma unroll
                for (int mt = 0; mt < 2; mt++) {
                    mma16816h(acc[mt][np * 2 + 0], ah[mt], bh0, bh1);
                    mma16816h(acc[mt][np * 2 + 1], ah[mt], bh2, bh3);
                }
            }
        }
        __syncthreads();
        if (kc + NSTAGE < 4) issue_chunk(kc + NSTAGE, st);
    }

    // ---- epilogue ----
    const int erow = lane >> 2;
    const int ecol = (lane & 3) * 2;
    #pragma unroll
    for (int mt = 0; mt < 2; mt++) {
        #pragma unroll
        for (int j = 0; j < 4; j++) {
            int col = warp_n + j * 8 + ecol;
            float b0 = 0.f, b1 = 0.f;
            if (c == 0) { b0 = __ldg(bsr + col); b1 = __ldg(bsr + col + 1); }
            int r0 = node0 + warp_m + mt * 16 + erow;
            int r1 = r0 + 8;
            if (r0 < N_NODES) {
                float2 v = make_float2(acc[mt][j][0] + b0, acc[mt][j][1] + b1);
                *(float2*)(out + (size_t)r0 * ROW_F + (size_t)c * H_DIM + col) = v;
            }
            if (r1 < N_NODES) {
                float2 v = make_float2(acc[mt][j][2] + b0, acc[mt][j][3] + b1);
                *(float2*)(out + (size_t)r1 * ROW_F + (size_t)c * H_DIM + col) = v;
            }
        }
    }
}

// ---------------------------------------------------------------------------
// Launch
// ---------------------------------------------------------------------------
extern "C" void kernel_launch(void* const* d_in, const int* in_sizes, int n_in,
                              void* d_out, int out_size) {
    const float* x      = (const float*)d_in[0];
    const void*  ei     = d_in[1];
    const float* Wsrel  = (const float*)d_in[2];
    const float* Wsroot = (const float*)d_in[3];
    const float* bsr    = (const float*)d_in[4];
    const float* Wvrel  = (const float*)d_in[5];
    const float* Wvroot = (const float*)d_in[6];
    float*       out    = (float*)d_out;

    cudaFuncSetAttribute(transform_mma_kernel,
                         cudaFuncAttributeMaxDynamicSharedMemorySize, SM_TOTAL);

    // Phase 0: dtype detect + weight fp16 + x fp16
    detect_dtype_kernel<<<1, 1>>>((const int*)ei);
    {
        dim3 grid(128, 4);
        prep_weights_kernel<<<grid, 256>>>(Wsrel, Wsroot, Wvrel, Wvroot);
    }
    {
        const size_t n4 = (size_t)N_NODES * ROW_F / 4;
        prep_x_kernel<<<(int)((n4 + 255) / 256), 256>>>(x);
    }

    // Phase 1: CSR build
    zero_cnt_kernel<<<(N_NODES + 255) / 256, 256>>>();
    hist_kernel<<<(E_EDGES + 255) / 256, 256>>>(ei);
    scan_kernel<<<1, 1024>>>();
    scatter_kernel<<<(E_EDGES + 255) / 256, 256>>>(ei);

    // Phase 2: CSR aggregation (fp16 gather, fp32 accumulate, fp16 out)
    csr_agg_kernel<<<(N_NODES + 3) / 4, 256>>>();

    // Phase 3: transform (fp16 HMMA, 3-stage cp.async pipeline)
    {
        dim3 grid((N_NODES + 127) / 128, 4);
        transform_mma_kernel<<<grid, 512, SM_TOTAL>>>(bsr, out);
    }
}